// round 13
// baseline (speedup 1.0000x reference)
#include <cuda_runtime.h>
#include <cuda_bf16.h>
#include <cstdint>
#include <math.h>

// Problem dims (fixed)
#define BB 1024
#define TT 64
#define DD 512
#define HH 512
#define N4H 2048
#define KBIG 1536   // 3*512 split-K
#define KHL  1024   // hi|lo storage per row
#define NCHUNK 24
#define STAGE_BYTES 32768   // 16KB A + 16KB B

// ---------------- device scratch ----------------
__device__ float g_zx[134217728];                  // [65536, 2048] X@W + bias
__device__ float g_z[2097152];                     // [1024, 2048] per-step h@U
__device__ float g_c[524288];                      // [1024, 512]
__device__ __nv_bfloat16 g_xhl[67108864];          // [65536, 1024] hi|lo of X
__device__ __nv_bfloat16 g_wb[3145728];            // [2048, 1536]  W^T split
__device__ __nv_bfloat16 g_ub[3145728];            // [2048, 1536]  U^T split
__device__ __nv_bfloat16 g_hhl[1048576];           // [1024, 1024]  hi|lo of h

// ---------------- helpers ----------------
#define SW128(x) ((x) ^ (((x) >> 3) & 0x70))

__device__ __forceinline__ uint32_t smem_u32(const void* p) {
    uint32_t a;
    asm("{ .reg .u64 t; cvta.to.shared.u64 t, %1; cvt.u32.u64 %0, t; }" : "=r"(a) : "l"(p));
    return a;
}
__device__ __forceinline__ void cp_async16(uint32_t dst, const void* src) {
    asm volatile("cp.async.cg.shared.global [%0], [%1], 16;" :: "r"(dst), "l"(src));
}
#define CP_COMMIT() asm volatile("cp.async.commit_group;" ::: "memory")
#define CP_WAIT1()  asm volatile("cp.async.wait_group 1;" ::: "memory")
#define CP_WAIT0()  asm volatile("cp.async.wait_group 0;" ::: "memory")

__device__ __forceinline__ void ldsm_x4(uint32_t& r0, uint32_t& r1, uint32_t& r2, uint32_t& r3,
                                        uint32_t addr) {
    asm volatile("ldmatrix.sync.aligned.m8n8.x4.shared.b16 {%0,%1,%2,%3}, [%4];"
                 : "=r"(r0), "=r"(r1), "=r"(r2), "=r"(r3) : "r"(addr));
}
__device__ __forceinline__ void mma_bf16(float* c, const uint32_t* a, const uint32_t* b) {
    asm volatile(
        "mma.sync.aligned.m16n8k16.row.col.f32.bf16.bf16.f32 "
        "{%0,%1,%2,%3}, {%4,%5,%6,%7}, {%8,%9}, {%0,%1,%2,%3};"
        : "+f"(c[0]), "+f"(c[1]), "+f"(c[2]), "+f"(c[3])
        : "r"(a[0]), "r"(a[1]), "r"(a[2]), "r"(a[3]), "r"(b[0]), "r"(b[1]));
}

// fast activations (MUFU-based, err ~1e-6; validated at rel_err 6.1e-6 in prior rounds)
__device__ __forceinline__ float sigf(float x) {
    return __fdividef(1.0f, 1.0f + __expf(-x));
}
__device__ __forceinline__ float tanh_(float x) {
    float ax = fabsf(x);
    float e  = __expf(2.0f * ax);
    float r  = 1.0f - __fdividef(2.0f, e + 1.0f);
    return copysignf(r, x);
}

// ---------------- split-K bf16 warp-MMA GEMM (R4-proven) ----------------
// C[M, 2048] (+bias) = A_hl @ Bt^T, K_eff = 1536, TN layout.
// A_hl: [M, 1024] bf16 (cols 0-511 = hi, 512-1023 = lo)
// Bt:   [2048, 1536] bf16 rows = N, K segments [hi | lo | hi]
// A k-chunk mapping: chunks 0-15 -> hi cols, 16-23 -> lo cols.
template <bool ADD_BIAS>
__global__ __launch_bounds__(256) void gemm3_kernel(
    const __nv_bfloat16* __restrict__ A,
    const __nv_bfloat16* __restrict__ Bt,
    const float* __restrict__ bias,
    float* __restrict__ C)
{
    extern __shared__ char dyn[];
    uint32_t dbase = smem_u32(dyn);
    dbase = (dbase + 1023u) & ~1023u;

    const int tid  = threadIdx.x;
    const int lane = tid & 31;
    const int wid  = tid >> 5;
    const int wm = (wid >> 2) * 64;
    const int wn = (wid & 3) * 32;
    const int bm = blockIdx.y * 128;
    const int bn = blockIdx.x * 128;

    const int g = lane >> 3;
    const int r = lane & 7;

    float acc[4][4][4];
    #pragma unroll
    for (int i = 0; i < 4; i++)
        #pragma unroll
        for (int j = 0; j < 4; j++)
            #pragma unroll
            for (int k = 0; k < 4; k++)
                acc[i][j][k] = 0.0f;

    auto issue_load = [&](int stage, int c) {
        const int seg  = c >> 3;
        const int acol = ((seg == 2) ? 512 : 0) + (c & 7) * 64;
        const int bcol = c * 64;
        const uint32_t sA = dbase + stage * STAGE_BYTES;
        const uint32_t sB = sA + 16384;
        #pragma unroll
        for (int j = 0; j < 4; j++) {
            int i = tid + j * 256;
            int row = i >> 3, c16 = i & 7;
            cp_async16(sA + SW128((uint32_t)(row * 128 + c16 * 16)),
                       A + (size_t)(bm + row) * KHL + acol + c16 * 8);
        }
        #pragma unroll
        for (int j = 0; j < 4; j++) {
            int i = tid + j * 256;
            int row = i >> 3, c16 = i & 7;
            cp_async16(sB + SW128((uint32_t)(row * 128 + c16 * 16)),
                       Bt + (size_t)(bn + row) * KBIG + bcol + c16 * 8);
        }
    };

    issue_load(0, 0); CP_COMMIT();
    issue_load(1, 1); CP_COMMIT();

    for (int c = 0; c < NCHUNK; c++) {
        if (c < NCHUNK - 1) { CP_WAIT1(); } else { CP_WAIT0(); }
        __syncthreads();

        const uint32_t sA = dbase + (c & 1) * STAGE_BYTES;
        const uint32_t sB = sA + 16384;

        #pragma unroll
        for (int kk = 0; kk < 4; kk++) {
            uint32_t af[4][4];
            #pragma unroll
            for (int mi = 0; mi < 4; mi++) {
                int row = wm + mi * 16 + (g & 1) * 8 + r;
                int col = kk * 16 + (g >> 1) * 8;
                ldsm_x4(af[mi][0], af[mi][1], af[mi][2], af[mi][3],
                        sA + SW128((uint32_t)(row * 128 + col * 2)));
            }
            uint32_t bf[4][2];
            #pragma unroll
            for (int half = 0; half < 2; half++) {
                int row = wn + half * 16 + (g >> 1) * 8 + r;
                int col = kk * 16 + (g & 1) * 8;
                ldsm_x4(bf[half * 2][0], bf[half * 2][1],
                        bf[half * 2 + 1][0], bf[half * 2 + 1][1],
                        sB + SW128((uint32_t)(row * 128 + col * 2)));
            }
            #pragma unroll
            for (int mi = 0; mi < 4; mi++)
                #pragma unroll
                for (int ni = 0; ni < 4; ni++)
                    mma_bf16(acc[mi][ni], af[mi], bf[ni]);
        }
        __syncthreads();
        if (c + 2 < NCHUNK) { issue_load(c & 1, c + 2); CP_COMMIT(); }
    }

    // ---- epilogue ----
    const int qrow = lane >> 2;
    const int qcol = (lane & 3) * 2;
    #pragma unroll
    for (int mi = 0; mi < 4; mi++) {
        #pragma unroll
        for (int ni = 0; ni < 4; ni++) {
            int row = bm + wm + mi * 16 + qrow;
            int col = bn + wn + ni * 8 + qcol;
            float b0 = ADD_BIAS ? bias[col]     : 0.0f;
            float b1 = ADD_BIAS ? bias[col + 1] : 0.0f;
            float2 v0 = { acc[mi][ni][0] + b0, acc[mi][ni][1] + b1 };
            float2 v1 = { acc[mi][ni][2] + b0, acc[mi][ni][3] + b1 };
            *reinterpret_cast<float2*>(C + (size_t)row * N4H + col) = v0;
            *reinterpret_cast<float2*>(C + (size_t)(row + 8) * N4H + col) = v1;
        }
    }
}

// ---------------- conversion kernels ----------------
__global__ __launch_bounds__(256) void conv_x_kernel(const float* __restrict__ X) {
    int idx = blockIdx.x * 256 + threadIdx.x;          // over 65536*512
    int m = idx >> 9, k = idx & 511;
    float v = X[idx];
    __nv_bfloat16 hi = __float2bfloat16(v);
    g_xhl[(size_t)m * KHL + k] = hi;
    g_xhl[(size_t)m * KHL + 512 + k] = __float2bfloat16(v - __bfloat162float(hi));
}

__global__ __launch_bounds__(256) void conv_w_kernel(const float* __restrict__ W,
                                                     __nv_bfloat16* __restrict__ Bt) {
    int idx = blockIdx.x * 256 + threadIdx.x;          // over 512*2048, W[k][n]
    int k = idx >> 11, n = idx & 2047;
    float v = W[idx];
    __nv_bfloat16 hi = __float2bfloat16(v);
    __nv_bfloat16 lo = __float2bfloat16(v - __bfloat162float(hi));
    Bt[(size_t)n * KBIG + k] = hi;
    Bt[(size_t)n * KBIG + 512 + k] = lo;
    Bt[(size_t)n * KBIG + 1024 + k] = hi;
}

// ---------------- fused gate / state update (vectorized, MUFU) ----------------
// 4 cells per thread; all loads/stores 16B (h hi/lo stores are 2x 4B pairs).
__global__ __launch_bounds__(256) void lstm_step_kernel(
    int t, int has_h, float* __restrict__ out)
{
    int v = blockIdx.x * 256 + threadIdx.x;            // 0 .. B*H/4-1
    int b = v >> 7;                                    // /128 (=512/4)
    int k4 = (v & 127) << 2;                           // k = k4..k4+3

    size_t zx_base = ((size_t)b * TT + t) * N4H + k4;
    float4 zi = *reinterpret_cast<const float4*>(g_zx + zx_base);
    float4 zf = *reinterpret_cast<const float4*>(g_zx + zx_base + 512);
    float4 zg = *reinterpret_cast<const float4*>(g_zx + zx_base + 1024);
    float4 zo = *reinterpret_cast<const float4*>(g_zx + zx_base + 1536);
    float4 cp = make_float4(0.f, 0.f, 0.f, 0.f);
    if (has_h) {
        size_t zh = (size_t)b * N4H + k4;
        const float4 hzi = *reinterpret_cast<const float4*>(g_z + zh);
        const float4 hzf = *reinterpret_cast<const float4*>(g_z + zh + 512);
        const float4 hzg = *reinterpret_cast<const float4*>(g_z + zh + 1024);
        const float4 hzo = *reinterpret_cast<const float4*>(g_z + zh + 1536);
        zi.x += hzi.x; zi.y += hzi.y; zi.z += hzi.z; zi.w += hzi.w;
        zf.x += hzf.x; zf.y += hzf.y; zf.z += hzf.z; zf.w += hzf.w;
        zg.x += hzg.x; zg.y += hzg.y; zg.z += hzg.z; zg.w += hzg.w;
        zo.x += hzo.x; zo.y += hzo.y; zo.z += hzo.z; zo.w += hzo.w;
        cp = *reinterpret_cast<const float4*>(g_c + (size_t)b * 512 + k4);
    }

    float zia[4] = { zi.x, zi.y, zi.z, zi.w };
    float zfa[4] = { zf.x, zf.y, zf.z, zf.w };
    float zga[4] = { zg.x, zg.y, zg.z, zg.w };
    float zoa[4] = { zo.x, zo.y, zo.z, zo.w };
    float cpa[4] = { cp.x, cp.y, cp.z, cp.w };
    float cn[4], hn[4];
    #pragma unroll
    for (int j = 0; j < 4; j++) {
        float i_ = sigf(zia[j]);
        float f_ = sigf(zfa[j]);
        float g_ = tanh_(zga[j]);
        float o_ = sigf(zoa[j]);
        cn[j] = f_ * cpa[j] + i_ * g_;
        hn[j] = o_ * tanh_(cn[j]);
    }

    *reinterpret_cast<float4*>(g_c + (size_t)b * 512 + k4) =
        make_float4(cn[0], cn[1], cn[2], cn[3]);
    *reinterpret_cast<float4*>(out + ((size_t)b * TT + t) * 512 + k4) =
        make_float4(hn[0], hn[1], hn[2], hn[3]);

    __nv_bfloat16 h0 = __float2bfloat16(hn[0]);
    __nv_bfloat16 h1 = __float2bfloat16(hn[1]);
    __nv_bfloat16 h2 = __float2bfloat16(hn[2]);
    __nv_bfloat16 h3 = __float2bfloat16(hn[3]);
    __nv_bfloat162 hi01 = __halves2bfloat162(h0, h1);
    __nv_bfloat162 hi23 = __halves2bfloat162(h2, h3);
    __nv_bfloat162 lo01 = __floats2bfloat162_rn(hn[0] - __bfloat162float(h0),
                                                hn[1] - __bfloat162float(h1));
    __nv_bfloat162 lo23 = __floats2bfloat162_rn(hn[2] - __bfloat162float(h2),
                                                hn[3] - __bfloat162float(h3));
    *reinterpret_cast<__nv_bfloat162*>(g_hhl + (size_t)b * KHL + k4) = hi01;
    *reinterpret_cast<__nv_bfloat162*>(g_hhl + (size_t)b * KHL + k4 + 2) = hi23;
    *reinterpret_cast<__nv_bfloat162*>(g_hhl + (size_t)b * KHL + 512 + k4) = lo01;
    *reinterpret_cast<__nv_bfloat162*>(g_hhl + (size_t)b * KHL + 512 + k4 + 2) = lo23;
}

// ---------------- launch ----------------
extern "C" void kernel_launch(void* const* d_in, const int* in_sizes, int n_in,
                              void* d_out, int out_size)
{
    const float* X    = (const float*)d_in[0];
    const float* W    = (const float*)d_in[1];
    const float* U    = (const float*)d_in[2];
    const float* bias = (const float*)d_in[3];
    float* out = (float*)d_out;

    float *zx_p, *z_p;
    __nv_bfloat16 *xhl_p, *wb_p, *ub_p, *hhl_p;
    cudaGetSymbolAddress((void**)&zx_p,  g_zx);
    cudaGetSymbolAddress((void**)&z_p,   g_z);
    cudaGetSymbolAddress((void**)&xhl_p, g_xhl);
    cudaGetSymbolAddress((void**)&wb_p,  g_wb);
    cudaGetSymbolAddress((void**)&ub_p,  g_ub);
    cudaGetSymbolAddress((void**)&hhl_p, g_hhl);

    const int SMEM = 2 * STAGE_BYTES + 1024;   // 66560
    cudaFuncSetAttribute(gemm3_kernel<true>,
                         cudaFuncAttributeMaxDynamicSharedMemorySize, SMEM);
    cudaFuncSetAttribute(gemm3_kernel<false>,
                         cudaFuncAttributeMaxDynamicSharedMemorySize, SMEM);

    // conversions
    conv_x_kernel<<<(65536 * 512) / 256, 256>>>(X);
    conv_w_kernel<<<(512 * 2048) / 256, 256>>>(W, wb_p);
    conv_w_kernel<<<(512 * 2048) / 256, 256>>>(U, ub_p);

    // Phase 1: Zx = X@W + bias  (M=65536, N=2048)
    gemm3_kernel<true><<<dim3(N4H / 128, 65536 / 128), 256, SMEM>>>(
        xhl_p, wb_p, bias, zx_p);

    const int step_blocks = (BB * HH / 4) / 256;   // 512

    // t = 0: h=0, c=0 -> no recurrent GEMM needed
    lstm_step_kernel<<<step_blocks, 256>>>(0, 0, out);

    // t = 1..63: z = h@U, then fused gate update
    dim3 grid2(N4H / 128, BB / 128);  // (16, 8) = 128 CTAs
    for (int t = 1; t < TT; t++) {
        gemm3_kernel<false><<<grid2, 256, SMEM>>>(hhl_p, ub_p, nullptr, z_p);
        lstm_step_kernel<<<step_blocks, 256>>>(t, 1, out);
    }
}

// round 14
// speedup vs baseline: 1.5398x; 1.5398x over previous
#include <cuda_runtime.h>
#include <cuda_bf16.h>
#include <cstdint>
#include <math.h>

// Problem dims (fixed)
#define BB 1024
#define TT 64
#define DD 512
#define HH 512
#define N4H 2048
#define KBIG 1536   // 3*512 split-K
#define KHL  1024   // hi|lo storage per row
#define NCHUNK 24
#define STAGE_BYTES 32768   // 16KB A + 16KB B
#define ZHALF 2097152       // floats per partial-z buffer [1024, 2048]

// ---------------- device scratch ----------------
__device__ float g_zx[134217728];                  // [65536, 2048] X@W + bias
__device__ float g_z[4194304];                     // 2 x [1024, 2048] split-K partials of h@U
__device__ float g_c[524288];                      // [1024, 512]
__device__ __nv_bfloat16 g_xhl[67108864];          // [65536, 1024] hi|lo of X
__device__ __nv_bfloat16 g_wb[3145728];            // [2048, 1536]  W^T split
__device__ __nv_bfloat16 g_ub[3145728];            // [2048, 1536]  U^T split
__device__ __nv_bfloat16 g_hhl[1048576];           // [1024, 1024]  hi|lo of h

// ---------------- helpers ----------------
#define SW128(x) ((x) ^ (((x) >> 3) & 0x70))

__device__ __forceinline__ uint32_t smem_u32(const void* p) {
    uint32_t a;
    asm("{ .reg .u64 t; cvta.to.shared.u64 t, %1; cvt.u32.u64 %0, t; }" : "=r"(a) : "l"(p));
    return a;
}
__device__ __forceinline__ void cp_async16(uint32_t dst, const void* src) {
    asm volatile("cp.async.cg.shared.global [%0], [%1], 16;" :: "r"(dst), "l"(src));
}
#define CP_COMMIT() asm volatile("cp.async.commit_group;" ::: "memory")
#define CP_WAIT1()  asm volatile("cp.async.wait_group 1;" ::: "memory")
#define CP_WAIT0()  asm volatile("cp.async.wait_group 0;" ::: "memory")

__device__ __forceinline__ void ldsm_x4(uint32_t& r0, uint32_t& r1, uint32_t& r2, uint32_t& r3,
                                        uint32_t addr) {
    asm volatile("ldmatrix.sync.aligned.m8n8.x4.shared.b16 {%0,%1,%2,%3}, [%4];"
                 : "=r"(r0), "=r"(r1), "=r"(r2), "=r"(r3) : "r"(addr));
}
__device__ __forceinline__ void mma_bf16(float* c, const uint32_t* a, const uint32_t* b) {
    asm volatile(
        "mma.sync.aligned.m16n8k16.row.col.f32.bf16.bf16.f32 "
        "{%0,%1,%2,%3}, {%4,%5,%6,%7}, {%8,%9}, {%0,%1,%2,%3};"
        : "+f"(c[0]), "+f"(c[1]), "+f"(c[2]), "+f"(c[3])
        : "r"(a[0]), "r"(a[1]), "r"(a[2]), "r"(a[3]), "r"(b[0]), "r"(b[1]));
}

// fast activations (MUFU-based, err ~1e-6; validated at rel_err 6.1e-6 in prior rounds)
__device__ __forceinline__ float sigf(float x) {
    return __fdividef(1.0f, 1.0f + __expf(-x));
}
__device__ __forceinline__ float tanh_(float x) {
    float ax = fabsf(x);
    float e  = __expf(2.0f * ax);
    float r  = 1.0f - __fdividef(2.0f, e + 1.0f);
    return copysignf(r, x);
}

// ---------------- split-K bf16 warp-MMA GEMM ----------------
// C_part[M, 2048] (+bias) = A_hl @ Bt^T over chunks [kz*nch, (kz+1)*nch).
// A_hl: [M, 1024] bf16 (cols 0-511 = hi, 512-1023 = lo)
// Bt:   [2048, 1536] bf16 rows = N, K segments [hi | lo | hi]
// A chunk mapping: chunks 0-15 -> hi cols, 16-23 -> lo cols.
// blockIdx.z selects the K-partition; partial written to C + z*ZHALF.
template <bool ADD_BIAS>
__global__ __launch_bounds__(256) void gemm3_kernel(
    const __nv_bfloat16* __restrict__ A,
    const __nv_bfloat16* __restrict__ Bt,
    const float* __restrict__ bias,
    float* __restrict__ C,
    int nch)
{
    extern __shared__ char dyn[];
    uint32_t dbase = smem_u32(dyn);
    dbase = (dbase + 1023u) & ~1023u;

    const int tid  = threadIdx.x;
    const int lane = tid & 31;
    const int wid  = tid >> 5;
    const int wm = (wid >> 2) * 64;
    const int wn = (wid & 3) * 32;
    const int bm = blockIdx.y * 128;
    const int bn = blockIdx.x * 128;
    const int c0 = blockIdx.z * nch;
    C += (size_t)blockIdx.z * ZHALF;

    const int g = lane >> 3;
    const int r = lane & 7;

    float acc[4][4][4];
    #pragma unroll
    for (int i = 0; i < 4; i++)
        #pragma unroll
        for (int j = 0; j < 4; j++)
            #pragma unroll
            for (int k = 0; k < 4; k++)
                acc[i][j][k] = 0.0f;

    auto issue_load = [&](int stage, int c) {
        const int seg  = c >> 3;
        const int acol = ((seg == 2) ? 512 : 0) + (c & 7) * 64;
        const int bcol = c * 64;
        const uint32_t sA = dbase + stage * STAGE_BYTES;
        const uint32_t sB = sA + 16384;
        #pragma unroll
        for (int j = 0; j < 4; j++) {
            int i = tid + j * 256;
            int row = i >> 3, c16 = i & 7;
            cp_async16(sA + SW128((uint32_t)(row * 128 + c16 * 16)),
                       A + (size_t)(bm + row) * KHL + acol + c16 * 8);
        }
        #pragma unroll
        for (int j = 0; j < 4; j++) {
            int i = tid + j * 256;
            int row = i >> 3, c16 = i & 7;
            cp_async16(sB + SW128((uint32_t)(row * 128 + c16 * 16)),
                       Bt + (size_t)(bn + row) * KBIG + bcol + c16 * 8);
        }
    };

    issue_load(0, c0); CP_COMMIT();
    issue_load(1, c0 + 1); CP_COMMIT();

    for (int c = 0; c < nch; c++) {
        if (c < nch - 1) { CP_WAIT1(); } else { CP_WAIT0(); }
        __syncthreads();

        const uint32_t sA = dbase + (c & 1) * STAGE_BYTES;
        const uint32_t sB = sA + 16384;

        #pragma unroll
        for (int kk = 0; kk < 4; kk++) {
            uint32_t af[4][4];
            #pragma unroll
            for (int mi = 0; mi < 4; mi++) {
                int row = wm + mi * 16 + (g & 1) * 8 + r;
                int col = kk * 16 + (g >> 1) * 8;
                ldsm_x4(af[mi][0], af[mi][1], af[mi][2], af[mi][3],
                        sA + SW128((uint32_t)(row * 128 + col * 2)));
            }
            uint32_t bf[4][2];
            #pragma unroll
            for (int half = 0; half < 2; half++) {
                int row = wn + half * 16 + (g >> 1) * 8 + r;
                int col = kk * 16 + (g & 1) * 8;
                ldsm_x4(bf[half * 2][0], bf[half * 2][1],
                        bf[half * 2 + 1][0], bf[half * 2 + 1][1],
                        sB + SW128((uint32_t)(row * 128 + col * 2)));
            }
            #pragma unroll
            for (int mi = 0; mi < 4; mi++)
                #pragma unroll
                for (int ni = 0; ni < 4; ni++)
                    mma_bf16(acc[mi][ni], af[mi], bf[ni]);
        }
        __syncthreads();
        if (c + 2 < nch) { issue_load(c & 1, c0 + c + 2); CP_COMMIT(); }
    }

    // ---- epilogue ----
    const int qrow = lane >> 2;
    const int qcol = (lane & 3) * 2;
    #pragma unroll
    for (int mi = 0; mi < 4; mi++) {
        #pragma unroll
        for (int ni = 0; ni < 4; ni++) {
            int row = bm + wm + mi * 16 + qrow;
            int col = bn + wn + ni * 8 + qcol;
            float b0 = ADD_BIAS ? bias[col]     : 0.0f;
            float b1 = ADD_BIAS ? bias[col + 1] : 0.0f;
            float2 v0 = { acc[mi][ni][0] + b0, acc[mi][ni][1] + b1 };
            float2 v1 = { acc[mi][ni][2] + b0, acc[mi][ni][3] + b1 };
            *reinterpret_cast<float2*>(C + (size_t)row * N4H + col) = v0;
            *reinterpret_cast<float2*>(C + (size_t)(row + 8) * N4H + col) = v1;
        }
    }
}

// ---------------- conversion kernels ----------------
__global__ __launch_bounds__(256) void conv_x_kernel(const float* __restrict__ X) {
    int idx = blockIdx.x * 256 + threadIdx.x;          // over 65536*512
    int m = idx >> 9, k = idx & 511;
    float v = X[idx];
    __nv_bfloat16 hi = __float2bfloat16(v);
    g_xhl[(size_t)m * KHL + k] = hi;
    g_xhl[(size_t)m * KHL + 512 + k] = __float2bfloat16(v - __bfloat162float(hi));
}

__global__ __launch_bounds__(256) void conv_w_kernel(const float* __restrict__ W,
                                                     __nv_bfloat16* __restrict__ Bt) {
    int idx = blockIdx.x * 256 + threadIdx.x;          // over 512*2048, W[k][n]
    int k = idx >> 11, n = idx & 2047;
    float v = W[idx];
    __nv_bfloat16 hi = __float2bfloat16(v);
    __nv_bfloat16 lo = __float2bfloat16(v - __bfloat162float(hi));
    Bt[(size_t)n * KBIG + k] = hi;
    Bt[(size_t)n * KBIG + 512 + k] = lo;
    Bt[(size_t)n * KBIG + 1024 + k] = hi;
}

// ---------------- fused gate / state update (vectorized, MUFU) ----------------
// 4 cells per thread; sums the two split-K partials of z.
__global__ __launch_bounds__(256) void lstm_step_kernel(
    int t, int has_h, float* __restrict__ out)
{
    int v = blockIdx.x * 256 + threadIdx.x;            // 0 .. B*H/4-1
    int b = v >> 7;                                    // /128 (=512/4)
    int k4 = (v & 127) << 2;                           // k = k4..k4+3

    size_t zx_base = ((size_t)b * TT + t) * N4H + k4;
    float4 zi = *reinterpret_cast<const float4*>(g_zx + zx_base);
    float4 zf = *reinterpret_cast<const float4*>(g_zx + zx_base + 512);
    float4 zg = *reinterpret_cast<const float4*>(g_zx + zx_base + 1024);
    float4 zo = *reinterpret_cast<const float4*>(g_zx + zx_base + 1536);
    float4 cp = make_float4(0.f, 0.f, 0.f, 0.f);
    if (has_h) {
        size_t zh = (size_t)b * N4H + k4;
        #pragma unroll
        for (int p = 0; p < 2; p++) {
            const float* zp = g_z + (size_t)p * ZHALF;
            const float4 hzi = *reinterpret_cast<const float4*>(zp + zh);
            const float4 hzf = *reinterpret_cast<const float4*>(zp + zh + 512);
            const float4 hzg = *reinterpret_cast<const float4*>(zp + zh + 1024);
            const float4 hzo = *reinterpret_cast<const float4*>(zp + zh + 1536);
            zi.x += hzi.x; zi.y += hzi.y; zi.z += hzi.z; zi.w += hzi.w;
            zf.x += hzf.x; zf.y += hzf.y; zf.z += hzf.z; zf.w += hzf.w;
            zg.x += hzg.x; zg.y += hzg.y; zg.z += hzg.z; zg.w += hzg.w;
            zo.x += hzo.x; zo.y += hzo.y; zo.z += hzo.z; zo.w += hzo.w;
        }
        cp = *reinterpret_cast<const float4*>(g_c + (size_t)b * 512 + k4);
    }

    float zia[4] = { zi.x, zi.y, zi.z, zi.w };
    float zfa[4] = { zf.x, zf.y, zf.z, zf.w };
    float zga[4] = { zg.x, zg.y, zg.z, zg.w };
    float zoa[4] = { zo.x, zo.y, zo.z, zo.w };
    float cpa[4] = { cp.x, cp.y, cp.z, cp.w };
    float cn[4], hn[4];
    #pragma unroll
    for (int j = 0; j < 4; j++) {
        float i_ = sigf(zia[j]);
        float f_ = sigf(zfa[j]);
        float g_ = tanh_(zga[j]);
        float o_ = sigf(zoa[j]);
        cn[j] = f_ * cpa[j] + i_ * g_;
        hn[j] = o_ * tanh_(cn[j]);
    }

    *reinterpret_cast<float4*>(g_c + (size_t)b * 512 + k4) =
        make_float4(cn[0], cn[1], cn[2], cn[3]);
    *reinterpret_cast<float4*>(out + ((size_t)b * TT + t) * 512 + k4) =
        make_float4(hn[0], hn[1], hn[2], hn[3]);

    __nv_bfloat16 h0 = __float2bfloat16(hn[0]);
    __nv_bfloat16 h1 = __float2bfloat16(hn[1]);
    __nv_bfloat16 h2 = __float2bfloat16(hn[2]);
    __nv_bfloat16 h3 = __float2bfloat16(hn[3]);
    __nv_bfloat162 hi01 = __halves2bfloat162(h0, h1);
    __nv_bfloat162 hi23 = __halves2bfloat162(h2, h3);
    __nv_bfloat162 lo01 = __floats2bfloat162_rn(hn[0] - __bfloat162float(h0),
                                                hn[1] - __bfloat162float(h1));
    __nv_bfloat162 lo23 = __floats2bfloat162_rn(hn[2] - __bfloat162float(h2),
                                                hn[3] - __bfloat162float(h3));
    *reinterpret_cast<__nv_bfloat162*>(g_hhl + (size_t)b * KHL + k4) = hi01;
    *reinterpret_cast<__nv_bfloat162*>(g_hhl + (size_t)b * KHL + k4 + 2) = hi23;
    *reinterpret_cast<__nv_bfloat162*>(g_hhl + (size_t)b * KHL + 512 + k4) = lo01;
    *reinterpret_cast<__nv_bfloat162*>(g_hhl + (size_t)b * KHL + 512 + k4 + 2) = lo23;
}

// ---------------- launch ----------------
extern "C" void kernel_launch(void* const* d_in, const int* in_sizes, int n_in,
                              void* d_out, int out_size)
{
    const float* X    = (const float*)d_in[0];
    const float* W    = (const float*)d_in[1];
    const float* U    = (const float*)d_in[2];
    const float* bias = (const float*)d_in[3];
    float* out = (float*)d_out;

    float *zx_p, *z_p;
    __nv_bfloat16 *xhl_p, *wb_p, *ub_p, *hhl_p;
    cudaGetSymbolAddress((void**)&zx_p,  g_zx);
    cudaGetSymbolAddress((void**)&z_p,   g_z);
    cudaGetSymbolAddress((void**)&xhl_p, g_xhl);
    cudaGetSymbolAddress((void**)&wb_p,  g_wb);
    cudaGetSymbolAddress((void**)&ub_p,  g_ub);
    cudaGetSymbolAddress((void**)&hhl_p, g_hhl);

    const int SMEM = 2 * STAGE_BYTES + 1024;   // 66560 -> 2 CTAs/SM
    cudaFuncSetAttribute(gemm3_kernel<true>,
                         cudaFuncAttributeMaxDynamicSharedMemorySize, SMEM);
    cudaFuncSetAttribute(gemm3_kernel<false>,
                         cudaFuncAttributeMaxDynamicSharedMemorySize, SMEM);

    // conversions
    conv_x_kernel<<<(65536 * 512) / 256, 256>>>(X);
    conv_w_kernel<<<(512 * 2048) / 256, 256>>>(W, wb_p);
    conv_w_kernel<<<(512 * 2048) / 256, 256>>>(U, ub_p);

    // Phase 1: Zx = X@W + bias  (M=65536, N=2048; gridDim.z=1, nch=24)
    gemm3_kernel<true><<<dim3(N4H / 128, 65536 / 128, 1), 256, SMEM>>>(
        xhl_p, wb_p, bias, zx_p, NCHUNK);

    const int step_blocks = (BB * HH / 4) / 256;   // 512

    // t = 0: h=0, c=0 -> no recurrent GEMM needed
    lstm_step_kernel<<<step_blocks, 256>>>(0, 0, out);

    // t = 1..63: split-K2 z = h@U (256 CTAs), then fused gate update
    dim3 grid2(N4H / 128, BB / 128, 2);  // (16, 8, 2) = 256 CTAs
    for (int t = 1; t < TT; t++) {
        gemm3_kernel<false><<<grid2, 256, SMEM>>>(hhl_p, ub_p, nullptr, z_p, NCHUNK / 2);
        lstm_step_kernel<<<step_blocks, 256>>>(t, 1, out);
    }
}

// round 16
// speedup vs baseline: 1.5542x; 1.0094x over previous
#include <cuda_runtime.h>
#include <cuda_bf16.h>
#include <cstdint>
#include <math.h>

// Problem dims (fixed)
#define BB 1024
#define TT 64
#define DD 512
#define HH 512
#define N4H 2048
#define KBIG 1536   // 3*512 split-K precision scheme
#define KHL  1024   // hi|lo storage per row
#define NCHUNK 24
#define STAGE_BYTES 32768   // 16KB A + 16KB B
#define ZHALF 2097152       // floats per partial-z buffer [1024, 2048]
#define NSEG 8              // phase-1 timestep segments (8 t each)

// ---------------- device scratch ----------------
__device__ float g_zx[134217728];                  // [64, 1024, 2048] X@W + bias (T-MAJOR)
__device__ float g_z[4194304];                     // 2 x [1024, 2048] split-K partials of h@U
__device__ float g_c[524288];                      // [1024, 512]
__device__ __nv_bfloat16 g_xhl[67108864];          // [65536, 1024] hi|lo of X (t-major rows)
__device__ __nv_bfloat16 g_wb[3145728];            // [2048, 1536]  W^T split
__device__ __nv_bfloat16 g_ub[3145728];            // [2048, 1536]  U^T split
__device__ __nv_bfloat16 g_hhl[1048576];           // [1024, 1024]  hi|lo of h

// ---------------- helpers ----------------
#define SW128(x) ((x) ^ (((x) >> 3) & 0x70))

__device__ __forceinline__ uint32_t smem_u32(const void* p) {
    uint32_t a;
    asm("{ .reg .u64 t; cvta.to.shared.u64 t, %1; cvt.u32.u64 %0, t; }" : "=r"(a) : "l"(p));
    return a;
}
__device__ __forceinline__ void cp_async16(uint32_t dst, const void* src) {
    asm volatile("cp.async.cg.shared.global [%0], [%1], 16;" :: "r"(dst), "l"(src));
}
#define CP_COMMIT() asm volatile("cp.async.commit_group;" ::: "memory")
#define CP_WAIT1()  asm volatile("cp.async.wait_group 1;" ::: "memory")
#define CP_WAIT0()  asm volatile("cp.async.wait_group 0;" ::: "memory")

__device__ __forceinline__ void ldsm_x4(uint32_t& r0, uint32_t& r1, uint32_t& r2, uint32_t& r3,
                                        uint32_t addr) {
    asm volatile("ldmatrix.sync.aligned.m8n8.x4.shared.b16 {%0,%1,%2,%3}, [%4];"
                 : "=r"(r0), "=r"(r1), "=r"(r2), "=r"(r3) : "r"(addr));
}
__device__ __forceinline__ void mma_bf16(float* c, const uint32_t* a, const uint32_t* b) {
    asm volatile(
        "mma.sync.aligned.m16n8k16.row.col.f32.bf16.bf16.f32 "
        "{%0,%1,%2,%3}, {%4,%5,%6,%7}, {%8,%9}, {%0,%1,%2,%3};"
        : "+f"(c[0]), "+f"(c[1]), "+f"(c[2]), "+f"(c[3])
        : "r"(a[0]), "r"(a[1]), "r"(a[2]), "r"(a[3]), "r"(b[0]), "r"(b[1]));
}

// fast activations (MUFU-based, err ~1e-6; validated in prior rounds)
__device__ __forceinline__ float sigf(float x) {
    return __fdividef(1.0f, 1.0f + __expf(-x));
}
__device__ __forceinline__ float tanh_(float x) {
    float ax = fabsf(x);
    float e  = __expf(2.0f * ax);
    float r  = 1.0f - __fdividef(2.0f, e + 1.0f);
    return copysignf(r, x);
}

// ---------------- GEMM inner machinery (shared by both kernels) ----------------
struct GemmCtx {
    uint32_t dbase;
    int tid, lane, wid, wm, wn, g, r;
};

__device__ __forceinline__ GemmCtx make_ctx(char* dyn) {
    GemmCtx cx;
    cx.dbase = (smem_u32(dyn) + 1023u) & ~1023u;
    cx.tid  = threadIdx.x;
    cx.lane = cx.tid & 31;
    cx.wid  = cx.tid >> 5;
    cx.wm = (cx.wid >> 2) * 64;
    cx.wn = (cx.wid & 3) * 32;
    cx.g = cx.lane >> 3;
    cx.r = cx.lane & 7;
    return cx;
}

__device__ __forceinline__ void issue_tiles(
    const GemmCtx& cx, const __nv_bfloat16* __restrict__ A,
    const __nv_bfloat16* __restrict__ Bt, int bm, int bn, int stage, int c)
{
    const int seg  = c >> 3;
    const int acol = ((seg == 2) ? 512 : 0) + (c & 7) * 64;
    const int bcol = c * 64;
    const uint32_t sA = cx.dbase + stage * STAGE_BYTES;
    const uint32_t sB = sA + 16384;
    #pragma unroll
    for (int j = 0; j < 4; j++) {
        int i = cx.tid + j * 256;
        int row = i >> 3, c16 = i & 7;
        cp_async16(sA + SW128((uint32_t)(row * 128 + c16 * 16)),
                   A + (size_t)(bm + row) * KHL + acol + c16 * 8);
    }
    #pragma unroll
    for (int j = 0; j < 4; j++) {
        int i = cx.tid + j * 256;
        int row = i >> 3, c16 = i & 7;
        cp_async16(sB + SW128((uint32_t)(row * 128 + c16 * 16)),
                   Bt + (size_t)(bn + row) * KBIG + bcol + c16 * 8);
    }
}

__device__ __forceinline__ void compute_chunk(const GemmCtx& cx, int buf, float acc[4][4][4]) {
    const uint32_t sA = cx.dbase + buf * STAGE_BYTES;
    const uint32_t sB = sA + 16384;
    #pragma unroll
    for (int kk = 0; kk < 4; kk++) {
        uint32_t af[4][4];
        #pragma unroll
        for (int mi = 0; mi < 4; mi++) {
            int row = cx.wm + mi * 16 + (cx.g & 1) * 8 + cx.r;
            int col = kk * 16 + (cx.g >> 1) * 8;
            ldsm_x4(af[mi][0], af[mi][1], af[mi][2], af[mi][3],
                    sA + SW128((uint32_t)(row * 128 + col * 2)));
        }
        uint32_t bf[4][2];
        #pragma unroll
        for (int half = 0; half < 2; half++) {
            int row = cx.wn + half * 16 + (cx.g >> 1) * 8 + cx.r;
            int col = kk * 16 + (cx.g & 1) * 8;
            ldsm_x4(bf[half * 2][0], bf[half * 2][1],
                    bf[half * 2 + 1][0], bf[half * 2 + 1][1],
                    sB + SW128((uint32_t)(row * 128 + col * 2)));
        }
        #pragma unroll
        for (int mi = 0; mi < 4; mi++)
            #pragma unroll
            for (int ni = 0; ni < 4; ni++)
                mma_bf16(acc[mi][ni], af[mi], bf[ni]);
    }
}

// ---------------- phase-1 segment GEMM: zx[m0+...] = X@W + bias ----------------
__global__ __launch_bounds__(256) void phase1_kernel(
    const __nv_bfloat16* __restrict__ A,
    const __nv_bfloat16* __restrict__ Bt,
    const float* __restrict__ bias,
    float* __restrict__ C,
    int m0)
{
    extern __shared__ char dyn[];
    GemmCtx cx = make_ctx(dyn);
    const int bm = m0 + blockIdx.y * 128;
    const int bn = blockIdx.x * 128;

    float acc[4][4][4];
    #pragma unroll
    for (int i = 0; i < 4; i++)
        #pragma unroll
        for (int j = 0; j < 4; j++)
            #pragma unroll
            for (int k = 0; k < 4; k++)
                acc[i][j][k] = 0.0f;

    issue_tiles(cx, A, Bt, bm, bn, 0, 0); CP_COMMIT();
    issue_tiles(cx, A, Bt, bm, bn, 1, 1); CP_COMMIT();

    for (int c = 0; c < NCHUNK; c++) {
        if (c < NCHUNK - 1) { CP_WAIT1(); } else { CP_WAIT0(); }
        __syncthreads();
        compute_chunk(cx, c & 1, acc);
        __syncthreads();
        if (c + 2 < NCHUNK) { issue_tiles(cx, A, Bt, bm, bn, c & 1, c + 2); CP_COMMIT(); }
    }

    const int qrow = cx.lane >> 2;
    const int qcol = (cx.lane & 3) * 2;
    #pragma unroll
    for (int mi = 0; mi < 4; mi++) {
        #pragma unroll
        for (int ni = 0; ni < 4; ni++) {
            int row = bm + cx.wm + mi * 16 + qrow;
            int col = bn + cx.wn + ni * 8 + qcol;
            float b0 = bias[col];
            float b1 = bias[col + 1];
            float2 v0 = { acc[mi][ni][0] + b0, acc[mi][ni][1] + b1 };
            float2 v1 = { acc[mi][ni][2] + b0, acc[mi][ni][3] + b1 };
            *reinterpret_cast<float2*>(C + (size_t)row * N4H + col) = v0;
            *reinterpret_cast<float2*>(C + (size_t)(row + 8) * N4H + col) = v1;
        }
    }
}

// ---------------- recurrent split-K2 GEMM: z partials = h@U ----------------
__global__ __launch_bounds__(256) void gemm_recur_kernel(
    const __nv_bfloat16* __restrict__ A,
    const __nv_bfloat16* __restrict__ Bt,
    float* __restrict__ C)
{
    extern __shared__ char dyn[];
    GemmCtx cx = make_ctx(dyn);
    const int bm = blockIdx.y * 128;
    const int bn = blockIdx.x * 128;
    const int c0 = blockIdx.z * (NCHUNK / 2);
    C += (size_t)blockIdx.z * ZHALF;

    float acc[4][4][4];
    #pragma unroll
    for (int i = 0; i < 4; i++)
        #pragma unroll
        for (int j = 0; j < 4; j++)
            #pragma unroll
            for (int k = 0; k < 4; k++)
                acc[i][j][k] = 0.0f;

    issue_tiles(cx, A, Bt, bm, bn, 0, c0); CP_COMMIT();
    issue_tiles(cx, A, Bt, bm, bn, 1, c0 + 1); CP_COMMIT();

    for (int c = 0; c < NCHUNK / 2; c++) {
        if (c < NCHUNK / 2 - 1) { CP_WAIT1(); } else { CP_WAIT0(); }
        __syncthreads();
        compute_chunk(cx, c & 1, acc);
        __syncthreads();
        if (c + 2 < NCHUNK / 2) { issue_tiles(cx, A, Bt, bm, bn, c & 1, c0 + c + 2); CP_COMMIT(); }
    }

    const int qrow = cx.lane >> 2;
    const int qcol = (cx.lane & 3) * 2;
    #pragma unroll
    for (int mi = 0; mi < 4; mi++) {
        #pragma unroll
        for (int ni = 0; ni < 4; ni++) {
            int row = bm + cx.wm + mi * 16 + qrow;
            int col = bn + cx.wn + ni * 8 + qcol;
            float2 v0 = { acc[mi][ni][0], acc[mi][ni][1] };
            float2 v1 = { acc[mi][ni][2], acc[mi][ni][3] };
            *reinterpret_cast<float2*>(C + (size_t)row * N4H + col) = v0;
            *reinterpret_cast<float2*>(C + (size_t)(row + 8) * N4H + col) = v1;
        }
    }
}

// ---------------- conversion kernels ----------------
// xhl rows T-MAJOR: row m = t*1024 + b holds X[b][t][:]
__global__ __launch_bounds__(256) void conv_x_kernel(const float* __restrict__ X) {
    int idx = blockIdx.x * 256 + threadIdx.x;          // over 65536*512 (output-linear)
    int m = idx >> 9, k = idx & 511;
    int t = m >> 10, b = m & 1023;
    float v = X[((size_t)b * TT + t) * DD + k];
    __nv_bfloat16 hi = __float2bfloat16(v);
    g_xhl[(size_t)m * KHL + k] = hi;
    g_xhl[(size_t)m * KHL + 512 + k] = __float2bfloat16(v - __bfloat162float(hi));
}

__global__ __launch_bounds__(256) void conv_w_kernel(const float* __restrict__ W,
                                                     __nv_bfloat16* __restrict__ Bt) {
    int idx = blockIdx.x * 256 + threadIdx.x;          // over 512*2048, W[k][n]
    int k = idx >> 11, n = idx & 2047;
    float v = W[idx];
    __nv_bfloat16 hi = __float2bfloat16(v);
    __nv_bfloat16 lo = __float2bfloat16(v - __bfloat162float(hi));
    Bt[(size_t)n * KBIG + k] = hi;
    Bt[(size_t)n * KBIG + 512 + k] = lo;
    Bt[(size_t)n * KBIG + 1024 + k] = hi;
}

// ---------------- fused gate / state update (vectorized, MUFU) ----------------
// zx is t-major: zx[(t*1024 + b)*2048 + col]. Sums 2 split-K partials of z.
__global__ __launch_bounds__(256) void lstm_step_kernel(
    int t, int has_h, float* __restrict__ out)
{
    int v = blockIdx.x * 256 + threadIdx.x;            // 0 .. B*H/4-1
    int b = v >> 7;
    int k4 = (v & 127) << 2;

    size_t zx_base = ((size_t)t * BB + b) * N4H + k4;
    float4 zi = *reinterpret_cast<const float4*>(g_zx + zx_base);
    float4 zf = *reinterpret_cast<const float4*>(g_zx + zx_base + 512);
    float4 zg = *reinterpret_cast<const float4*>(g_zx + zx_base + 1024);
    float4 zo = *reinterpret_cast<const float4*>(g_zx + zx_base + 1536);
    float4 cp = make_float4(0.f, 0.f, 0.f, 0.f);
    if (has_h) {
        size_t zh = (size_t)b * N4H + k4;
        #pragma unroll
        for (int p = 0; p < 2; p++) {
            const float* zp = g_z + (size_t)p * ZHALF;
            const float4 hzi = *reinterpret_cast<const float4*>(zp + zh);
            const float4 hzf = *reinterpret_cast<const float4*>(zp + zh + 512);
            const float4 hzg = *reinterpret_cast<const float4*>(zp + zh + 1024);
            const float4 hzo = *reinterpret_cast<const float4*>(zp + zh + 1536);
            zi.x += hzi.x; zi.y += hzi.y; zi.z += hzi.z; zi.w += hzi.w;
            zf.x += hzf.x; zf.y += hzf.y; zf.z += hzf.z; zf.w += hzf.w;
            zg.x += hzg.x; zg.y += hzg.y; zg.z += hzg.z; zg.w += hzg.w;
            zo.x += hzo.x; zo.y += hzo.y; zo.z += hzo.z; zo.w += hzo.w;
        }
        cp = *reinterpret_cast<const float4*>(g_c + (size_t)b * 512 + k4);
    }

    float zia[4] = { zi.x, zi.y, zi.z, zi.w };
    float zfa[4] = { zf.x, zf.y, zf.z, zf.w };
    float zga[4] = { zg.x, zg.y, zg.z, zg.w };
    float zoa[4] = { zo.x, zo.y, zo.z, zo.w };
    float cpa[4] = { cp.x, cp.y, cp.z, cp.w };
    float cn[4], hn[4];
    #pragma unroll
    for (int j = 0; j < 4; j++) {
        float i_ = sigf(zia[j]);
        float f_ = sigf(zfa[j]);
        float g_ = tanh_(zga[j]);
        float o_ = sigf(zoa[j]);
        cn[j] = f_ * cpa[j] + i_ * g_;
        hn[j] = o_ * tanh_(cn[j]);
    }

    *reinterpret_cast<float4*>(g_c + (size_t)b * 512 + k4) =
        make_float4(cn[0], cn[1], cn[2], cn[3]);
    *reinterpret_cast<float4*>(out + ((size_t)b * TT + t) * 512 + k4) =
        make_float4(hn[0], hn[1], hn[2], hn[3]);

    __nv_bfloat16 h0 = __float2bfloat16(hn[0]);
    __nv_bfloat16 h1 = __float2bfloat16(hn[1]);
    __nv_bfloat16 h2 = __float2bfloat16(hn[2]);
    __nv_bfloat16 h3 = __float2bfloat16(hn[3]);
    __nv_bfloat162 hi01 = __halves2bfloat162(h0, h1);
    __nv_bfloat162 hi23 = __halves2bfloat162(h2, h3);
    __nv_bfloat162 lo01 = __floats2bfloat162_rn(hn[0] - __bfloat162float(h0),
                                                hn[1] - __bfloat162float(h1));
    __nv_bfloat162 lo23 = __floats2bfloat162_rn(hn[2] - __bfloat162float(h2),
                                                hn[3] - __bfloat162float(h3));
    *reinterpret_cast<__nv_bfloat162*>(g_hhl + (size_t)b * KHL + k4) = hi01;
    *reinterpret_cast<__nv_bfloat162*>(g_hhl + (size_t)b * KHL + k4 + 2) = hi23;
    *reinterpret_cast<__nv_bfloat162*>(g_hhl + (size_t)b * KHL + 512 + k4) = lo01;
    *reinterpret_cast<__nv_bfloat162*>(g_hhl + (size_t)b * KHL + 512 + k4 + 2) = lo23;
}

// ---------------- launch ----------------
extern "C" void kernel_launch(void* const* d_in, const int* in_sizes, int n_in,
                              void* d_out, int out_size)
{
    const float* X    = (const float*)d_in[0];
    const float* W    = (const float*)d_in[1];
    const float* U    = (const float*)d_in[2];
    const float* bias = (const float*)d_in[3];
    float* out = (float*)d_out;

    float *zx_p, *z_p;
    __nv_bfloat16 *xhl_p, *wb_p, *ub_p, *hhl_p;
    cudaGetSymbolAddress((void**)&zx_p,  g_zx);
    cudaGetSymbolAddress((void**)&z_p,   g_z);
    cudaGetSymbolAddress((void**)&xhl_p, g_xhl);
    cudaGetSymbolAddress((void**)&wb_p,  g_wb);
    cudaGetSymbolAddress((void**)&ub_p,  g_ub);
    cudaGetSymbolAddress((void**)&hhl_p, g_hhl);

    const int SMEM = 2 * STAGE_BYTES + 1024;   // 66560 -> 2 CTAs/SM
    cudaFuncSetAttribute(phase1_kernel,
                         cudaFuncAttributeMaxDynamicSharedMemorySize, SMEM);
    cudaFuncSetAttribute(gemm_recur_kernel,
                         cudaFuncAttributeMaxDynamicSharedMemorySize, SMEM);

    // ---- fork infrastructure (leaked intentionally; capture-safe) ----
    int prLeast = 0, prGreatest = 0;
    cudaDeviceGetStreamPriorityRange(&prLeast, &prGreatest);
    cudaStream_t sA = 0;
    if (cudaStreamCreateWithPriority(&sA, cudaStreamNonBlocking, prLeast) != cudaSuccess)
        sA = 0;   // fallback: fully serial on the capture stream
    cudaEvent_t eFork, eSeg[NSEG];
    cudaEventCreateWithFlags(&eFork, cudaEventDisableTiming);
    for (int s = 0; s < NSEG; s++)
        cudaEventCreateWithFlags(&eSeg[s], cudaEventDisableTiming);

    // conversions on the main (capture) stream
    conv_x_kernel<<<(65536 * 512) / 256, 256>>>(X);
    conv_w_kernel<<<(512 * 2048) / 256, 256>>>(W, wb_p);
    conv_w_kernel<<<(512 * 2048) / 256, 256>>>(U, ub_p);

    // fork: phase-1 segments on low-priority stream sA
    cudaEventRecord(eFork, 0);
    if (sA != 0) cudaStreamWaitEvent(sA, eFork, 0);
    for (int s = 0; s < NSEG; s++) {
        phase1_kernel<<<dim3(16, (65536 / NSEG) / 128), 256, SMEM, sA>>>(
            xhl_p, wb_p, bias, zx_p, s * (65536 / NSEG));
        cudaEventRecord(eSeg[s], sA);
    }

    const int step_blocks = (BB * HH / 4) / 256;   // 512
    dim3 grid2(N4H / 128, BB / 128, 2);            // (16, 8, 2) = 256 CTAs

    // recurrence on the main stream; wait segment events as zx timesteps are needed
    cudaStreamWaitEvent(0, eSeg[0], 0);
    lstm_step_kernel<<<step_blocks, 256>>>(0, 0, out);
    for (int t = 1; t < TT; t++) {
        gemm_recur_kernel<<<grid2, 256, SMEM>>>(hhl_p, ub_p, z_p);
        if ((t & 7) == 0) cudaStreamWaitEvent(0, eSeg[t >> 3], 0);
        lstm_step_kernel<<<step_blocks, 256>>>(t, 1, out);
    }
}